// round 12
// baseline (speedup 1.0000x reference)
#include <cuda_runtime.h>
#include <cstdint>

#define HW 65536           // 256*256
#define NB 8
#define NC 32
#define NBC 256

#define MIX_BLOCKS 1024    // 128 chunks (512 px each) x 8 batches
#define POOL_BLOCKS 1024   // 256 (b,c) x 4 row-chunks

__device__ __align__(16) float g_feat[NB * NC * HW];
__device__ float g_pp[NBC * 4 * 25];
__device__ float g_filt[NBC * 25];

// ---------------------------------------------------------------------------
// Kernel 1: FUSED channel-mix + adaptive-pool-partials, block-specialized.
// Mix path: warp = ALL 32 out-channels x 64 px (1 float2/lane, 64 scalar
//   accs). Per i-step: 1 LDG.64 + 8 LDS.128 (weights, broadcast) + 64 FFMA
//   -> 2x the FFMA-per-load of R9. ~88 regs -> 2 blocks/SM (4 warps/SMSP);
//   per unroll-4 window each SMSP carries ~2048 FFMA-cycles vs 577-cyc DRAM
//   latency -> memory fully hidden, FMA pipe saturated.
// Pool path: DRAM-streaming partial pooling of x; backfills mix tail waves.
// grid = 2048, block = 256
// ---------------------------------------------------------------------------
__global__ __launch_bounds__(256) void mixpool_kernel(
    const float* __restrict__ x,
    const float* __restrict__ w,
    const float* __restrict__ bias)
{
    if (blockIdx.x < MIX_BLOCKS) {
        // ------------------------- mix path -------------------------
        __shared__ float ws[32 * 32];   // [i][o] transposed
        __shared__ float bs[32];

        int tid = threadIdx.x;
        for (int idx = tid; idx < 1024; idx += 256) {
            int i = idx >> 5, o = idx & 31;
            ws[i * 32 + o] = w[o * 32 + i];
        }
        if (tid < 32)
            bs[tid] = bias[tid];
        __syncthreads();

        int wid  = tid >> 5;
        int lane = tid & 31;

        int b  = blockIdx.x >> 7;      // batch
        int cx = blockIdx.x & 127;     // 512-px chunk within image
        size_t pixpair = (size_t)cx * 256 + wid * 32 + lane;  // float2 idx
        const float2* xp = (const float2*)x
                         + (size_t)b * (NC * (HW / 2)) + pixpair;

        float ax[32], ay[32];
#pragma unroll
        for (int k = 0; k < 32; k++) {
            float bv = bs[k];
            ax[k] = bv;
            ay[k] = bv;
        }

#pragma unroll 4
        for (int i = 0; i < 32; i++) {
            float2 xv = xp[(size_t)i * (HW / 2)];
            const float4* wr = (const float4*)(ws + i * 32);
#pragma unroll
            for (int q = 0; q < 8; q++) {
                float4 wv = wr[q];
                ax[q * 4 + 0] = fmaf(wv.x, xv.x, ax[q * 4 + 0]);
                ay[q * 4 + 0] = fmaf(wv.x, xv.y, ay[q * 4 + 0]);
                ax[q * 4 + 1] = fmaf(wv.y, xv.x, ax[q * 4 + 1]);
                ay[q * 4 + 1] = fmaf(wv.y, xv.y, ay[q * 4 + 1]);
                ax[q * 4 + 2] = fmaf(wv.z, xv.x, ax[q * 4 + 2]);
                ay[q * 4 + 2] = fmaf(wv.z, xv.y, ay[q * 4 + 2]);
                ax[q * 4 + 3] = fmaf(wv.w, xv.x, ax[q * 4 + 3]);
                ay[q * 4 + 3] = fmaf(wv.w, xv.y, ay[q * 4 + 3]);
            }
        }

        float2* fb = (float2*)g_feat + (size_t)b * (NC * (HW / 2)) + pixpair;
#pragma unroll
        for (int k = 0; k < 32; k++)
            fb[(size_t)k * (HW / 2)] = make_float2(ax[k], ay[k]);

    } else {
        // ------------------------- pool path -------------------------
        // Row bins [0,52)[51,103)[102,154)[153,205)[204,256) (overlap).
        __shared__ float pool[25];
        int idx = blockIdx.x - MIX_BLOCKS;
        int bc = idx >> 2;             // (b*32 + channel)
        int q  = idx & 3;              // 64-row chunk
        int w_ = threadIdx.x;          // column
        if (w_ < 25) pool[w_] = 0.0f;
        __syncthreads();

        const float* img = x + (size_t)bc * HW + (size_t)q * 64 * 256;

        float cs[5] = {0.f, 0.f, 0.f, 0.f, 0.f};
#pragma unroll
        for (int r = 0; r < 64; r++) {
            int h = q * 64 + r;
            float v = img[r * 256 + w_];
            if (h < 52)              cs[0] += v;
            if (h >= 51 && h < 103)  cs[1] += v;
            if (h >= 102 && h < 154) cs[2] += v;
            if (h >= 153 && h < 205) cs[3] += v;
            if (h >= 204)            cs[4] += v;
        }

#pragma unroll
        for (int l = 0; l < 5; l++) {
            int s0 = (l * 256) / 5;
            int e0 = ((l + 1) * 256 + 4) / 5;
            if (w_ >= s0 && w_ < e0) {
#pragma unroll
                for (int k = 0; k < 5; k++)
                    if (cs[k] != 0.0f)
                        atomicAdd(&pool[k * 5 + l], cs[k]);
            }
        }
        __syncthreads();
        if (w_ < 25)
            g_pp[(bc * 4 + q) * 25 + w_] = pool[w_];
    }
}

// ---------------------------------------------------------------------------
// Kernel 2: filt[b,o,kl] = bias[o] + sum_i w[o,i] * px[b,i,kl]
// (pooling commutes with the 1x1 conv: pool matrix is row-stochastic)
// grid = 8, block = 800
// ---------------------------------------------------------------------------
__global__ void filt_kernel(const float* __restrict__ w,
                            const float* __restrict__ bias)
{
    __shared__ float spx[800];
    int b = blockIdx.x;
    int t = threadIdx.x;
    int i  = t / 25;
    int kl = t - i * 25;

    float s = 0.0f;
#pragma unroll
    for (int q = 0; q < 4; q++)
        s += g_pp[((b * 32 + i) * 4 + q) * 25 + kl];
    spx[t] = s * (1.0f / 2704.0f);
    __syncthreads();

    float acc = bias[i];
#pragma unroll
    for (int ic = 0; ic < 32; ic++)
        acc += w[i * 32 + ic] * spx[ic * 25 + kl];
    g_filt[b * 800 + t] = acc;
}

// ---------------------------------------------------------------------------
// Kernel 3: depthwise 5x5 'same' conv (best measured config: 38 us,
// occ 91%, issue 70%). 64x32 tile, 36x68 halo, thread = 1 col x 8 rows,
// division-free halo staging.
// grid = (32, 256), block = 256
// ---------------------------------------------------------------------------
__global__ __launch_bounds__(256) void conv_kernel(float* __restrict__ out)
{
    __shared__ float sh[36 * 68];

    int bc  = blockIdx.y;
    int tile = blockIdx.x;
    int tx0 = (tile & 3) * 64;
    int ty0 = (tile >> 2) * 32;

    const float* img = g_feat + (size_t)bc * HW;

    float f[25];
#pragma unroll
    for (int t = 0; t < 25; t++) f[t] = g_filt[bc * 25 + t];

    {
        int c  = threadIdx.x & 63;
        int r0 = threadIdx.x >> 6;
        int gx = tx0 + c - 2;
        bool cin = (unsigned)gx < 256u;
#pragma unroll
        for (int k = 0; k < 9; k++) {
            int r = r0 + k * 4;
            int gy = ty0 + r - 2;
            float v = 0.0f;
            if (cin && (unsigned)gy < 256u)
                v = img[gy * 256 + gx];
            sh[r * 68 + c] = v;
        }
        int c2 = 64 + (threadIdx.x & 3);
        int r2 = threadIdx.x >> 2;
        if (r2 < 36) {
            int gy = ty0 + r2 - 2;
            int gx2 = tx0 + c2 - 2;
            float v = 0.0f;
            if ((unsigned)gy < 256u && (unsigned)gx2 < 256u)
                v = img[gy * 256 + gx2];
            sh[r2 * 68 + c2] = v;
        }
    }
    __syncthreads();

    int x  = threadIdx.x & 63;
    int ys = (threadIdx.x >> 6) * 8;

    float acc[8];
#pragma unroll
    for (int j = 0; j < 8; j++) acc[j] = 0.0f;

#pragma unroll
    for (int r = 0; r < 12; r++) {
        const float* row = sh + (ys + r) * 68 + x;
        float v0 = row[0];
        float v1 = row[1];
        float v2 = row[2];
        float v3 = row[3];
        float v4 = row[4];
#pragma unroll
        for (int ky = 0; ky < 5; ky++) {
            int j = r - ky;
            if (j >= 0 && j < 8) {
                acc[j] += v0 * f[ky * 5 + 0];
                acc[j] += v1 * f[ky * 5 + 1];
                acc[j] += v2 * f[ky * 5 + 2];
                acc[j] += v3 * f[ky * 5 + 3];
                acc[j] += v4 * f[ky * 5 + 4];
            }
        }
    }

    float* op = out + (size_t)bc * HW + (size_t)(ty0 + ys) * 256 + tx0 + x;
#pragma unroll
    for (int j = 0; j < 8; j++)
        op[j * 256] = acc[j];
}

// ---------------------------------------------------------------------------
extern "C" void kernel_launch(void* const* d_in, const int* in_sizes, int n_in,
                              void* d_out, int out_size)
{
    const float* x    = (const float*)d_in[0];   // [8, 32, 256, 256]
    const float* w    = (const float*)d_in[1];   // [32, 32]
    const float* bias = (const float*)d_in[2];   // [32]
    float* out = (float*)d_out;                  // [8, 32, 256, 256]

    mixpool_kernel<<<MIX_BLOCKS + POOL_BLOCKS, 256>>>(x, w, bias);
    filt_kernel<<<NB, 800>>>(w, bias);
    conv_kernel<<<dim3(32, NBC), 256>>>(out);
}

// round 13
// speedup vs baseline: 1.0124x; 1.0124x over previous
#include <cuda_runtime.h>
#include <cstdint>

#define HW 65536           // 256*256
#define NB 8
#define NC 32
#define NBC 256

#define MIX_BLOCKS 2048    // 256 px-chunks x 8 batches (R9 config)
#define POOL_BLOCKS 1024   // 256 (b,c) x 4 row-chunks

__device__ __align__(16) float g_feat[NB * NC * HW];
__device__ float g_pp[NBC * 4 * 25];
__device__ float g_filt[NBC * 25];

// ---------------------------------------------------------------------------
// Kernel 1: FUSED channel-mix + adaptive-pool-partials, block-specialized.
// Mix path (R9 shape, tightened): warp = 16 och x 64 px, 32 scalar accs.
//   Per i-step: 1 LDG.64 + 4 LDS.128 (weights, broadcast) + 32 FFMA applied
//   DIRECTLY on float4 components (no wv[] register copy -> no MOV tax).
//   __launch_bounds__(256,4) caps regs at 64 -> 4 blocks/SM (8 warps/SMSP).
// Pool path: DRAM-streaming partial pooling of x; backfills mix tail waves.
// grid = 3072, block = 256
// ---------------------------------------------------------------------------
__global__ __launch_bounds__(256, 4) void mixpool_kernel(
    const float* __restrict__ x,
    const float* __restrict__ w,
    const float* __restrict__ bias)
{
    if (blockIdx.x < MIX_BLOCKS) {
        // ------------------------- mix path -------------------------
        __shared__ float ws[32 * 32];   // [i][o] transposed
        __shared__ float bs[32];

        int tid = threadIdx.x;
        for (int idx = tid; idx < 1024; idx += 256) {
            int i = idx >> 5, o = idx & 31;
            ws[i * 32 + o] = w[o * 32 + i];
        }
        if (tid < 32)
            bs[tid] = bias[tid];
        __syncthreads();

        int wid  = tid >> 5;
        int lane = tid & 31;
        int g = wid & 1;               // och group: g*16 .. g*16+15
        int s = wid >> 1;              // px segment (64 px each)

        int b  = blockIdx.x >> 8;      // batch
        int cx = blockIdx.x & 255;     // 256-px chunk within image
        size_t pixpair = (size_t)cx * 128 + s * 32 + lane;   // float2 idx
        const float2* xp = (const float2*)x
                         + (size_t)b * (NC * (HW / 2)) + pixpair;

        float ax[16], ay[16];
#pragma unroll
        for (int k = 0; k < 16; k++) {
            float bv = bs[g * 16 + k];
            ax[k] = bv;
            ay[k] = bv;
        }

#pragma unroll 4
        for (int i = 0; i < 32; i++) {
            float2 xv = xp[(size_t)i * (HW / 2)];
            const float4* wr = (const float4*)(ws + i * 32 + g * 16);
#pragma unroll
            for (int q = 0; q < 4; q++) {
                float4 wv = wr[q];
                ax[q * 4 + 0] = fmaf(wv.x, xv.x, ax[q * 4 + 0]);
                ay[q * 4 + 0] = fmaf(wv.x, xv.y, ay[q * 4 + 0]);
                ax[q * 4 + 1] = fmaf(wv.y, xv.x, ax[q * 4 + 1]);
                ay[q * 4 + 1] = fmaf(wv.y, xv.y, ay[q * 4 + 1]);
                ax[q * 4 + 2] = fmaf(wv.z, xv.x, ax[q * 4 + 2]);
                ay[q * 4 + 2] = fmaf(wv.z, xv.y, ay[q * 4 + 2]);
                ax[q * 4 + 3] = fmaf(wv.w, xv.x, ax[q * 4 + 3]);
                ay[q * 4 + 3] = fmaf(wv.w, xv.y, ay[q * 4 + 3]);
            }
        }

        float2* fb = (float2*)g_feat + (size_t)b * (NC * (HW / 2)) + pixpair;
#pragma unroll
        for (int k = 0; k < 16; k++)
            fb[(size_t)(g * 16 + k) * (HW / 2)] = make_float2(ax[k], ay[k]);

    } else {
        // ------------------------- pool path -------------------------
        // Row bins [0,52)[51,103)[102,154)[153,205)[204,256) (overlap).
        __shared__ float pool[25];
        int idx = blockIdx.x - MIX_BLOCKS;
        int bc = idx >> 2;             // (b*32 + channel)
        int q  = idx & 3;              // 64-row chunk
        int w_ = threadIdx.x;          // column
        if (w_ < 25) pool[w_] = 0.0f;
        __syncthreads();

        const float* img = x + (size_t)bc * HW + (size_t)q * 64 * 256;

        float cs[5] = {0.f, 0.f, 0.f, 0.f, 0.f};
#pragma unroll
        for (int r = 0; r < 64; r++) {
            int h = q * 64 + r;
            float v = img[r * 256 + w_];
            if (h < 52)              cs[0] += v;
            if (h >= 51 && h < 103)  cs[1] += v;
            if (h >= 102 && h < 154) cs[2] += v;
            if (h >= 153 && h < 205) cs[3] += v;
            if (h >= 204)            cs[4] += v;
        }

#pragma unroll
        for (int l = 0; l < 5; l++) {
            int s0 = (l * 256) / 5;
            int e0 = ((l + 1) * 256 + 4) / 5;
            if (w_ >= s0 && w_ < e0) {
#pragma unroll
                for (int k = 0; k < 5; k++)
                    if (cs[k] != 0.0f)
                        atomicAdd(&pool[k * 5 + l], cs[k]);
            }
        }
        __syncthreads();
        if (w_ < 25)
            g_pp[(bc * 4 + q) * 25 + w_] = pool[w_];
    }
}

// ---------------------------------------------------------------------------
// Kernel 2: filt[b,o,kl] = bias[o] + sum_i w[o,i] * px[b,i,kl]
// (pooling commutes with the 1x1 conv: pool matrix is row-stochastic)
// grid = 8, block = 800
// ---------------------------------------------------------------------------
__global__ void filt_kernel(const float* __restrict__ w,
                            const float* __restrict__ bias)
{
    __shared__ float spx[800];
    int b = blockIdx.x;
    int t = threadIdx.x;
    int i  = t / 25;
    int kl = t - i * 25;

    float s = 0.0f;
#pragma unroll
    for (int q = 0; q < 4; q++)
        s += g_pp[((b * 32 + i) * 4 + q) * 25 + kl];
    spx[t] = s * (1.0f / 2704.0f);
    __syncthreads();

    float acc = bias[i];
#pragma unroll
    for (int ic = 0; ic < 32; ic++)
        acc += w[i * 32 + ic] * spx[ic * 25 + kl];
    g_filt[b * 800 + t] = acc;
}

// ---------------------------------------------------------------------------
// Kernel 3: depthwise 5x5 'same' conv (best measured config: 38 us,
// occ 91%, issue 70%). 64x32 tile, 36x68 halo, thread = 1 col x 8 rows,
// division-free halo staging.
// grid = (32, 256), block = 256
// ---------------------------------------------------------------------------
__global__ __launch_bounds__(256) void conv_kernel(float* __restrict__ out)
{
    __shared__ float sh[36 * 68];

    int bc  = blockIdx.y;
    int tile = blockIdx.x;
    int tx0 = (tile & 3) * 64;
    int ty0 = (tile >> 2) * 32;

    const float* img = g_feat + (size_t)bc * HW;

    float f[25];
#pragma unroll
    for (int t = 0; t < 25; t++) f[t] = g_filt[bc * 25 + t];

    {
        int c  = threadIdx.x & 63;
        int r0 = threadIdx.x >> 6;
        int gx = tx0 + c - 2;
        bool cin = (unsigned)gx < 256u;
#pragma unroll
        for (int k = 0; k < 9; k++) {
            int r = r0 + k * 4;
            int gy = ty0 + r - 2;
            float v = 0.0f;
            if (cin && (unsigned)gy < 256u)
                v = img[gy * 256 + gx];
            sh[r * 68 + c] = v;
        }
        int c2 = 64 + (threadIdx.x & 3);
        int r2 = threadIdx.x >> 2;
        if (r2 < 36) {
            int gy = ty0 + r2 - 2;
            int gx2 = tx0 + c2 - 2;
            float v = 0.0f;
            if ((unsigned)gy < 256u && (unsigned)gx2 < 256u)
                v = img[gy * 256 + gx2];
            sh[r2 * 68 + c2] = v;
        }
    }
    __syncthreads();

    int x  = threadIdx.x & 63;
    int ys = (threadIdx.x >> 6) * 8;

    float acc[8];
#pragma unroll
    for (int j = 0; j < 8; j++) acc[j] = 0.0f;

#pragma unroll
    for (int r = 0; r < 12; r++) {
        const float* row = sh + (ys + r) * 68 + x;
        float v0 = row[0];
        float v1 = row[1];
        float v2 = row[2];
        float v3 = row[3];
        float v4 = row[4];
#pragma unroll
        for (int ky = 0; ky < 5; ky++) {
            int j = r - ky;
            if (j >= 0 && j < 8) {
                acc[j] += v0 * f[ky * 5 + 0];
                acc[j] += v1 * f[ky * 5 + 1];
                acc[j] += v2 * f[ky * 5 + 2];
                acc[j] += v3 * f[ky * 5 + 3];
                acc[j] += v4 * f[ky * 5 + 4];
            }
        }
    }

    float* op = out + (size_t)bc * HW + (size_t)(ty0 + ys) * 256 + tx0 + x;
#pragma unroll
    for (int j = 0; j < 8; j++)
        op[j * 256] = acc[j];
}

// ---------------------------------------------------------------------------
extern "C" void kernel_launch(void* const* d_in, const int* in_sizes, int n_in,
                              void* d_out, int out_size)
{
    const float* x    = (const float*)d_in[0];   // [8, 32, 256, 256]
    const float* w    = (const float*)d_in[1];   // [32, 32]
    const float* bias = (const float*)d_in[2];   // [32]
    float* out = (float*)d_out;                  // [8, 32, 256, 256]

    mixpool_kernel<<<MIX_BLOCKS + POOL_BLOCKS, 256>>>(x, w, bias);
    filt_kernel<<<NB, 800>>>(w, bias);
    conv_kernel<<<dim3(32, NBC), 256>>>(out);
}